// round 3
// baseline (speedup 1.0000x reference)
#include <cuda_runtime.h>

// Problem shape (fixed by the dataset)
#define BB 16
#define NN 512
#define FF 256
#define M_TOT (BB * NN)   // 8192

// Scratch: y = adj @ x (8 MB) and deg = rowsum(adj)
__device__ float g_y[M_TOT * FF];
__device__ float g_deg[M_TOT];

// ---------------------------------------------------------------------------
// Kernel 1: y[b,i,:] = sum_j adj[b,i,j] * x[b,j,:]   (adj binary -> masked sum)
//           deg[b,i] = sum_j adj[b,i,j]
// CTA = (b, 32 i-rows). 8 warps x 4 rows. x staged through smem in 64-row
// tiles; zeros skipped via warp-uniform ballot.
// ---------------------------------------------------------------------------
#define ICH 32
#define JT  64

__global__ __launch_bounds__(256) void agg_x_kernel(
    const float* __restrict__ X,
    const float* __restrict__ ADJ,
    float* __restrict__ Y,
    float* __restrict__ DEG)
{
    extern __shared__ float xt[];   // [JT][FF] = 64 KB

    const int b    = blockIdx.y;
    const int i0   = blockIdx.x * ICH;
    const int t    = threadIdx.x;
    const int w    = t >> 5;        // warp 0..7, each owns 4 i rows
    const int lane = t & 31;        // lane owns features lane*8 .. lane*8+7

    const float* xb = X + (size_t)b * NN * FF;

    float acc[4][8];
    int   degc[4];
#pragma unroll
    for (int ii = 0; ii < 4; ii++) {
        degc[ii] = 0;
#pragma unroll
        for (int c = 0; c < 8; c++) acc[ii][c] = 0.0f;
    }

    for (int jt = 0; jt < NN / JT; jt++) {
        // Cooperative load of x[b, jt*64 .. +63, :] into smem (4096 float4)
        const float4* src = reinterpret_cast<const float4*>(xb + (size_t)jt * JT * FF);
        float4* dst = reinterpret_cast<float4*>(xt);
#pragma unroll
        for (int r = 0; r < 16; r++)
            dst[t + r * 256] = src[t + r * 256];
        __syncthreads();

#pragma unroll
        for (int ii = 0; ii < 4; ii++) {
            const float* arow = ADJ + ((size_t)b * NN + i0 + w * 4 + ii) * NN + jt * JT;
#pragma unroll
            for (int g = 0; g < 2; g++) {
                float av = arow[g * 32 + lane];
                unsigned mask = __ballot_sync(0xffffffffu, av > 0.0f);
                degc[ii] += __popc(mask);
                while (mask) {
                    int j = g * 32 + (__ffs(mask) - 1);
                    mask &= mask - 1;
                    const float* hr = xt + j * FF + lane * 8;
                    float4 h0 = *reinterpret_cast<const float4*>(hr);
                    float4 h1 = *reinterpret_cast<const float4*>(hr + 4);
                    acc[ii][0] += h0.x; acc[ii][1] += h0.y;
                    acc[ii][2] += h0.z; acc[ii][3] += h0.w;
                    acc[ii][4] += h1.x; acc[ii][5] += h1.y;
                    acc[ii][6] += h1.z; acc[ii][7] += h1.w;
                }
            }
        }
        __syncthreads();
    }

#pragma unroll
    for (int ii = 0; ii < 4; ii++) {
        const int m = b * NN + i0 + w * 4 + ii;
        float* yr = Y + (size_t)m * FF + lane * 8;
        float4 o0 = {acc[ii][0], acc[ii][1], acc[ii][2], acc[ii][3]};
        float4 o1 = {acc[ii][4], acc[ii][5], acc[ii][6], acc[ii][7]};
        *reinterpret_cast<float4*>(yr)     = o0;
        *reinterpret_cast<float4*>(yr + 4) = o1;
        if (lane == 0) DEG[m] = (float)degc[ii];
    }
}

// ---------------------------------------------------------------------------
// Kernel 2: fused GEMM + gate + blend
//   hp[m,n]  = leaky( sum_k y[m,k]*W[n,k] + deg[m]*bias[n], 0.2 )
//   coeff[m] = sigmoid( x[m,:].gw_x + hp[m,:].gw_h + gb )
//   out      = coeff*x + (1-coeff)*hp
// BM=32, BN=256 (full row per CTA -> warp-level gate reduction), BK=16.
// 256 threads: tx=lane (cols tx*4 and 128+tx*4), ty=warp (rows ty*4..+3).
// ---------------------------------------------------------------------------
#define BM2 32
#define BK2 16

__global__ __launch_bounds__(256) void gemm_gate_kernel(
    const float* __restrict__ Y,
    const float* __restrict__ W,
    const float* __restrict__ Wb,
    const float* __restrict__ DEG,
    const float* __restrict__ X,
    const float* __restrict__ GW,
    const float* __restrict__ GB,
    float* __restrict__ OUT)
{
    __shared__ float As[BK2][BM2];      // 2 KB
    __shared__ float Bs[BK2][FF];       // 16 KB

    const int t  = threadIdx.x;
    const int tx = t & 31;              // lane
    const int ty = t >> 5;              // warp 0..7
    const int m0 = blockIdx.x * BM2;

    const float4* Y4 = reinterpret_cast<const float4*>(Y);
    const float4* W4 = reinterpret_cast<const float4*>(W);

    float acc[4][8];
#pragma unroll
    for (int i = 0; i < 4; i++)
#pragma unroll
        for (int j = 0; j < 8; j++) acc[i][j] = 0.0f;

    for (int kt = 0; kt < FF; kt += BK2) {
        // A tile: 32 rows x 16 k = 128 float4; threads 0..127 load 1 each
        if (t < 128) {
            int row = t >> 2;
            int kg  = (t & 3) * 4;
            float4 v = Y4[(size_t)(m0 + row) * (FF / 4) + (kt >> 2) + (t & 3)];
            As[kg + 0][row] = v.x;
            As[kg + 1][row] = v.y;
            As[kg + 2][row] = v.z;
            As[kg + 3][row] = v.w;
        }
        // B tile: W[n, kt..kt+15] -> Bs[k][n]; 1024 float4, 4 per thread
#pragma unroll
        for (int p = 0; p < 4; p++) {
            int e  = t + p * 256;
            int n  = e >> 2;
            int kg = (e & 3) * 4;
            float4 v = W4[(size_t)n * (FF / 4) + (kt >> 2) + (e & 3)];
            Bs[kg + 0][n] = v.x;
            Bs[kg + 1][n] = v.y;
            Bs[kg + 2][n] = v.z;
            Bs[kg + 3][n] = v.w;
        }
        __syncthreads();

#pragma unroll
        for (int k = 0; k < BK2; k++) {
            float4 a  = *reinterpret_cast<const float4*>(&As[k][ty * 4]);
            float4 b0 = *reinterpret_cast<const float4*>(&Bs[k][tx * 4]);
            float4 b1 = *reinterpret_cast<const float4*>(&Bs[k][128 + tx * 4]);
            float av[4] = {a.x, a.y, a.z, a.w};
#pragma unroll
            for (int i = 0; i < 4; i++) {
                acc[i][0] += av[i] * b0.x;
                acc[i][1] += av[i] * b0.y;
                acc[i][2] += av[i] * b0.z;
                acc[i][3] += av[i] * b0.w;
                acc[i][4] += av[i] * b1.x;
                acc[i][5] += av[i] * b1.y;
                acc[i][6] += av[i] * b1.z;
                acc[i][7] += av[i] * b1.w;
            }
        }
        __syncthreads();
    }

    // Epilogue: bias via deg, leaky relu, gate reduction, blend, store
    float4 bias0 = *reinterpret_cast<const float4*>(&Wb[tx * 4]);
    float4 bias1 = *reinterpret_cast<const float4*>(&Wb[128 + tx * 4]);
    float4 gwx0  = *reinterpret_cast<const float4*>(&GW[tx * 4]);
    float4 gwx1  = *reinterpret_cast<const float4*>(&GW[128 + tx * 4]);
    float4 gwh0  = *reinterpret_cast<const float4*>(&GW[FF + tx * 4]);
    float4 gwh1  = *reinterpret_cast<const float4*>(&GW[FF + 128 + tx * 4]);
    const float gb = GB[0];

#pragma unroll
    for (int i = 0; i < 4; i++) {
        const int m = m0 + ty * 4 + i;
        const float dg = DEG[m];

        float hp[8];
        hp[0] = acc[i][0] + dg * bias0.x;
        hp[1] = acc[i][1] + dg * bias0.y;
        hp[2] = acc[i][2] + dg * bias0.z;
        hp[3] = acc[i][3] + dg * bias0.w;
        hp[4] = acc[i][4] + dg * bias1.x;
        hp[5] = acc[i][5] + dg * bias1.y;
        hp[6] = acc[i][6] + dg * bias1.z;
        hp[7] = acc[i][7] + dg * bias1.w;
#pragma unroll
        for (int c = 0; c < 8; c++)
            hp[c] = (hp[c] > 0.0f) ? hp[c] : 0.2f * hp[c];

        const float* xr = X + (size_t)m * FF;
        float4 x0 = *reinterpret_cast<const float4*>(xr + tx * 4);
        float4 x1 = *reinterpret_cast<const float4*>(xr + 128 + tx * 4);
        float xv[8] = {x0.x, x0.y, x0.z, x0.w, x1.x, x1.y, x1.z, x1.w};

        // gate partial: x.gw_x + hp.gw_h over this lane's 8 columns
        float p = xv[0] * gwx0.x + xv[1] * gwx0.y + xv[2] * gwx0.z + xv[3] * gwx0.w
                + xv[4] * gwx1.x + xv[5] * gwx1.y + xv[6] * gwx1.z + xv[7] * gwx1.w
                + hp[0] * gwh0.x + hp[1] * gwh0.y + hp[2] * gwh0.z + hp[3] * gwh0.w
                + hp[4] * gwh1.x + hp[5] * gwh1.y + hp[6] * gwh1.z + hp[7] * gwh1.w;
#pragma unroll
        for (int off = 16; off > 0; off >>= 1)
            p += __shfl_xor_sync(0xffffffffu, p, off);

        float coeff = 1.0f / (1.0f + expf(-(p + gb)));
        float om = 1.0f - coeff;

        float4 o0, o1;
        o0.x = coeff * xv[0] + om * hp[0];
        o0.y = coeff * xv[1] + om * hp[1];
        o0.z = coeff * xv[2] + om * hp[2];
        o0.w = coeff * xv[3] + om * hp[3];
        o1.x = coeff * xv[4] + om * hp[4];
        o1.y = coeff * xv[5] + om * hp[5];
        o1.z = coeff * xv[6] + om * hp[6];
        o1.w = coeff * xv[7] + om * hp[7];

        float* orow = OUT + (size_t)m * FF;
        *reinterpret_cast<float4*>(orow + tx * 4)       = o0;
        *reinterpret_cast<float4*>(orow + 128 + tx * 4) = o1;
    }
}

// ---------------------------------------------------------------------------
extern "C" void kernel_launch(void* const* d_in, const int* in_sizes, int n_in,
                              void* d_out, int out_size)
{
    const float* x    = (const float*)d_in[0];   // [16,512,256]
    const float* adj  = (const float*)d_in[1];   // [16,512,512]
    const float* W_w  = (const float*)d_in[2];   // [256,256]
    const float* W_b  = (const float*)d_in[3];   // [256]
    // d_in[4] = A : dead code in the reference (attention never used)
    const float* gw   = (const float*)d_in[5];   // [1,512]
    const float* gb   = (const float*)d_in[6];   // [1]
    float* out = (float*)d_out;

    float* y;   cudaGetSymbolAddress((void**)&y,   g_y);
    float* deg; cudaGetSymbolAddress((void**)&deg, g_deg);

    cudaFuncSetAttribute(agg_x_kernel,
                         cudaFuncAttributeMaxDynamicSharedMemorySize,
                         JT * FF * sizeof(float));
    dim3 grid1(NN / ICH, BB);                    // (16, 16) = 256 CTAs
    agg_x_kernel<<<grid1, 256, JT * FF * sizeof(float)>>>(x, adj, y, deg);

    dim3 grid2(M_TOT / BM2);                     // 256 CTAs
    gemm_gate_kernel<<<grid2, 256>>>(y, W_w, W_b, deg, x, gw, gb, out);
}

// round 4
// speedup vs baseline: 1.1186x; 1.1186x over previous
#include <cuda_runtime.h>

// Problem shape (fixed by the dataset)
#define BB 16
#define NN 512
#define FF 256
#define M_TOT (BB * NN)   // 8192

typedef unsigned long long ull;

// Scratch
__device__ float g_y[M_TOT * FF];      // adj @ x
__device__ float g_hp[M_TOT * FF];     // leaky((adj@x)W + deg*b)
__device__ float g_deg[M_TOT];         // rowsum(adj)
__device__ float g_gatep[M_TOT * 4];   // per-ntile gate partials (hp . gwh)

// ---- packed f32x2 helpers (FFMA2 path ptxas won't emit on its own) --------
#define PACK_X2(d, lo, hi) \
    asm("mov.b64 %0, {%1, %2};" : "=l"(d) : "r"(__float_as_uint(lo)), "r"(__float_as_uint(hi)))
#define UNPK_X2(lo, hi, s) do { unsigned _l, _h; \
    asm("mov.b64 {%0, %1}, %2;" : "=r"(_l), "=r"(_h) : "l"(s)); \
    lo = __uint_as_float(_l); hi = __uint_as_float(_h); } while (0)
#define ADD_X2I(acc, a) \
    asm("add.rn.f32x2 %0, %0, %1;" : "+l"(acc) : "l"(a))
#define FMA_X2I(acc, a, b) \
    asm("fma.rn.f32x2 %0, %1, %2, %0;" : "+l"(acc) : "l"(a), "l"(b))

// ---------------------------------------------------------------------------
// Kernel 1: y[b,i,f] = sum_j adj[b,i,j] * x[b,j,f]  (binary adj, ballot skip)
//           deg[b,i] = sum_j adj[b,i,j]
// Grid (NN/ICH, BB, 2): z = feature half. CTA = 8 warps x 4 i-rows each,
// lane owns 4 features of its half. x staged in 64-row x 128-feat smem tiles.
// ---------------------------------------------------------------------------
#define ICH 32
#define JT  64
#define FH  128

__global__ __launch_bounds__(256) void agg_x_kernel(
    const float* __restrict__ X,
    const float* __restrict__ ADJ,
    float* __restrict__ Y,
    float* __restrict__ DEG)
{
    __shared__ float xt[JT * FH];   // 32 KB

    const int b    = blockIdx.y;
    const int i0   = blockIdx.x * ICH;
    const int fs   = blockIdx.z;
    const int t    = threadIdx.x;
    const int w    = t >> 5;
    const int lane = t & 31;

    const float4* xb4 = reinterpret_cast<const float4*>(X + (size_t)b * NN * FF + fs * FH);
    float4* xt4 = reinterpret_cast<float4*>(xt);

    ull acc2[4][2] = {{0ull, 0ull}, {0ull, 0ull}, {0ull, 0ull}, {0ull, 0ull}};
    int degc[4] = {0, 0, 0, 0};

    for (int jt = 0; jt < NN / JT; jt++) {
        // load x[b, jt*64 .. +63, fs*128 .. +128): 2048 float4, 8 per thread
#pragma unroll
        for (int p = 0; p < 8; p++) {
            int e   = t + p * 256;
            int row = e >> 5;          // 0..63
            int c   = e & 31;          // float4 within row
            xt4[row * (FH / 4) + c] = xb4[(size_t)(jt * JT + row) * (FF / 4) + c];
        }
        __syncthreads();

#pragma unroll
        for (int ii = 0; ii < 4; ii++) {
            const float* arow = ADJ + ((size_t)b * NN + i0 + w * 4 + ii) * NN + jt * JT;
#pragma unroll
            for (int g = 0; g < 2; g++) {
                float av = arow[g * 32 + lane];
                unsigned mask = __ballot_sync(0xffffffffu, av > 0.0f);
                degc[ii] += __popc(mask);
                while (mask) {
                    int j = g * 32 + (__ffs(mask) - 1);
                    mask &= mask - 1;
                    float4 h = *reinterpret_cast<const float4*>(xt + j * FH + lane * 4);
                    ull h01, h23;
                    PACK_X2(h01, h.x, h.y);
                    PACK_X2(h23, h.z, h.w);
                    ADD_X2I(acc2[ii][0], h01);
                    ADD_X2I(acc2[ii][1], h23);
                }
            }
        }
        __syncthreads();
    }

#pragma unroll
    for (int ii = 0; ii < 4; ii++) {
        const int m = b * NN + i0 + w * 4 + ii;
        float4 o;
        UNPK_X2(o.x, o.y, acc2[ii][0]);
        UNPK_X2(o.z, o.w, acc2[ii][1]);
        *reinterpret_cast<float4*>(Y + (size_t)m * FF + fs * FH + lane * 4) = o;
        if (fs == 0 && lane == 0) DEG[m] = (float)degc[ii];
    }
}

// ---------------------------------------------------------------------------
// Kernel 2: hp[m,n] = leaky( sum_k y[m,k]*W[n,k] + deg[m]*bias[n], 0.2 )
//           gatep[m, ntile] = sum_{n in tile} hp[m,n] * gwh[n]
// BM=128, BN=64, BK=16, 256 threads, 8x4 micro done as 4 row-pair FFMA2.
// ---------------------------------------------------------------------------
#define BM 128
#define BN 64
#define BK 16

__global__ __launch_bounds__(256) void gemm_hp_kernel(
    const float* __restrict__ Y,
    const float* __restrict__ W,
    const float* __restrict__ Wb,
    const float* __restrict__ DEG,
    const float* __restrict__ GW,
    float* __restrict__ HP,
    float* __restrict__ GATEP)
{
    __shared__ float As[BK][BM];
    __shared__ float Bs[BK][BN];

    const int t  = threadIdx.x;
    const int tx = t & 15;
    const int ty = t >> 4;
    const int m0 = blockIdx.y * BM;
    const int n0 = blockIdx.x * BN;

    const float4* Y4 = reinterpret_cast<const float4*>(Y);
    const float4* W4 = reinterpret_cast<const float4*>(W);

    ull acc2[4][4];
#pragma unroll
    for (int p = 0; p < 4; p++)
#pragma unroll
        for (int j = 0; j < 4; j++) acc2[p][j] = 0ull;

    for (int kt = 0; kt < FF; kt += BK) {
#pragma unroll
        for (int p = 0; p < 2; p++) {
            int e   = t + p * 256;
            int row = e >> 2;
            int kg  = (e & 3) * 4;
            float4 v = Y4[(size_t)(m0 + row) * (FF / 4) + (kt >> 2) + (e & 3)];
            As[kg + 0][row] = v.x;
            As[kg + 1][row] = v.y;
            As[kg + 2][row] = v.z;
            As[kg + 3][row] = v.w;
        }
        {
            int row = t >> 2;
            int kg  = (t & 3) * 4;
            float4 v = W4[(size_t)(n0 + row) * (FF / 4) + (kt >> 2) + (t & 3)];
            Bs[kg + 0][row] = v.x;
            Bs[kg + 1][row] = v.y;
            Bs[kg + 2][row] = v.z;
            Bs[kg + 3][row] = v.w;
        }
        __syncthreads();

#pragma unroll
        for (int k = 0; k < BK; k++) {
            float4 a0 = *reinterpret_cast<const float4*>(&As[k][ty * 8]);
            float4 a1 = *reinterpret_cast<const float4*>(&As[k][ty * 8 + 4]);
            float4 bv = *reinterpret_cast<const float4*>(&Bs[k][tx * 4]);
            ull aa[4], bb[4];
            PACK_X2(aa[0], a0.x, a0.y);
            PACK_X2(aa[1], a0.z, a0.w);
            PACK_X2(aa[2], a1.x, a1.y);
            PACK_X2(aa[3], a1.z, a1.w);
            PACK_X2(bb[0], bv.x, bv.x);
            PACK_X2(bb[1], bv.y, bv.y);
            PACK_X2(bb[2], bv.z, bv.z);
            PACK_X2(bb[3], bv.w, bv.w);
#pragma unroll
            for (int p = 0; p < 4; p++)
#pragma unroll
                for (int j = 0; j < 4; j++)
                    FMA_X2I(acc2[p][j], aa[p], bb[j]);
        }
        __syncthreads();
    }

    // Epilogue: deg*bias, leaky, store hp, gate partials
    float4 bias = *reinterpret_cast<const float4*>(&Wb[n0 + tx * 4]);
    float4 gwh  = *reinterpret_cast<const float4*>(&GW[FF + n0 + tx * 4]);

    float gpart[8];
#pragma unroll
    for (int p = 0; p < 4; p++) {
        float r0[4], r1[4];
#pragma unroll
        for (int j = 0; j < 4; j++) UNPK_X2(r0[j], r1[j], acc2[p][j]);

#pragma unroll
        for (int s = 0; s < 2; s++) {
            const int i = p * 2 + s;
            const int m = m0 + ty * 8 + i;
            const float dg = DEG[m];
            float* rr = s ? r1 : r0;
            float hp[4];
            hp[0] = rr[0] + dg * bias.x;
            hp[1] = rr[1] + dg * bias.y;
            hp[2] = rr[2] + dg * bias.z;
            hp[3] = rr[3] + dg * bias.w;
#pragma unroll
            for (int j = 0; j < 4; j++)
                hp[j] = (hp[j] > 0.0f) ? hp[j] : 0.2f * hp[j];

            float4 o = {hp[0], hp[1], hp[2], hp[3]};
            *reinterpret_cast<float4*>(HP + (size_t)m * FF + n0 + tx * 4) = o;

            gpart[i] = hp[0] * gwh.x + hp[1] * gwh.y + hp[2] * gwh.z + hp[3] * gwh.w;
        }
    }
    // reduce over the 16 tx lanes sharing each row group (offsets stay in-half)
#pragma unroll
    for (int i = 0; i < 8; i++)
#pragma unroll
        for (int off = 8; off > 0; off >>= 1)
            gpart[i] += __shfl_xor_sync(0xffffffffu, gpart[i], off);

    if (tx == 0) {
#pragma unroll
        for (int i = 0; i < 8; i++)
            GATEP[(size_t)(m0 + ty * 8 + i) * 4 + blockIdx.x] = gpart[i];
    }
}

// ---------------------------------------------------------------------------
// Kernel 3: coeff[m] = sigmoid( x[m,:].gwx + sum(gatep[m,:]) + gb )
//           out = coeff*x + (1-coeff)*hp
// 8 warps/CTA, 2 rows per warp, grid = M_TOT/16 = 512.
// ---------------------------------------------------------------------------
__global__ __launch_bounds__(256) void blend_kernel(
    const float* __restrict__ X,
    const float* __restrict__ HP,
    const float* __restrict__ GATEP,
    const float* __restrict__ GW,
    const float* __restrict__ GB,
    float* __restrict__ OUT)
{
    const int t    = threadIdx.x;
    const int w    = t >> 5;
    const int lane = t & 31;
    const int m0   = blockIdx.x * 16;

    float4 gx0 = *reinterpret_cast<const float4*>(&GW[lane * 8]);
    float4 gx1 = *reinterpret_cast<const float4*>(&GW[lane * 8 + 4]);
    const float gb = GB[0];

#pragma unroll
    for (int r = 0; r < 2; r++) {
        const int m = m0 + w * 2 + r;
        const float* xr = X + (size_t)m * FF + lane * 8;
        float4 x0 = *reinterpret_cast<const float4*>(xr);
        float4 x1 = *reinterpret_cast<const float4*>(xr + 4);

        float p = x0.x * gx0.x + x0.y * gx0.y + x0.z * gx0.z + x0.w * gx0.w
                + x1.x * gx1.x + x1.y * gx1.y + x1.z * gx1.z + x1.w * gx1.w;
#pragma unroll
        for (int off = 16; off > 0; off >>= 1)
            p += __shfl_xor_sync(0xffffffffu, p, off);

        const float* gp = GATEP + (size_t)m * 4;
        float g = p + gp[0] + gp[1] + gp[2] + gp[3] + gb;
        float coeff = 1.0f / (1.0f + expf(-g));
        float om = 1.0f - coeff;

        const float* hr = HP + (size_t)m * FF + lane * 8;
        float4 h0 = *reinterpret_cast<const float4*>(hr);
        float4 h1 = *reinterpret_cast<const float4*>(hr + 4);

        float4 o0, o1;
        o0.x = coeff * x0.x + om * h0.x;
        o0.y = coeff * x0.y + om * h0.y;
        o0.z = coeff * x0.z + om * h0.z;
        o0.w = coeff * x0.w + om * h0.w;
        o1.x = coeff * x1.x + om * h1.x;
        o1.y = coeff * x1.y + om * h1.y;
        o1.z = coeff * x1.z + om * h1.z;
        o1.w = coeff * x1.w + om * h1.w;

        float* orow = OUT + (size_t)m * FF + lane * 8;
        *reinterpret_cast<float4*>(orow)     = o0;
        *reinterpret_cast<float4*>(orow + 4) = o1;
    }
}

// ---------------------------------------------------------------------------
extern "C" void kernel_launch(void* const* d_in, const int* in_sizes, int n_in,
                              void* d_out, int out_size)
{
    const float* x    = (const float*)d_in[0];   // [16,512,256]
    const float* adj  = (const float*)d_in[1];   // [16,512,512]
    const float* W_w  = (const float*)d_in[2];   // [256,256]
    const float* W_b  = (const float*)d_in[3];   // [256]
    // d_in[4] = A : dead code in the reference
    const float* gw   = (const float*)d_in[5];   // [1,512]
    const float* gb   = (const float*)d_in[6];   // [1]
    float* out = (float*)d_out;

    float* y;     cudaGetSymbolAddress((void**)&y,     g_y);
    float* hp;    cudaGetSymbolAddress((void**)&hp,    g_hp);
    float* deg;   cudaGetSymbolAddress((void**)&deg,   g_deg);
    float* gatep; cudaGetSymbolAddress((void**)&gatep, g_gatep);

    dim3 grid1(NN / ICH, BB, 2);                 // 512 CTAs
    agg_x_kernel<<<grid1, 256>>>(x, adj, y, deg);

    dim3 grid2(FF / BN, M_TOT / BM);             // (4, 64) = 256 CTAs
    gemm_hp_kernel<<<grid2, 256>>>(y, W_w, W_b, deg, gw, hp, gatep);

    blend_kernel<<<M_TOT / 16, 256>>>(x, hp, gatep, gw, gb, out);
}

// round 8
// speedup vs baseline: 1.1941x; 1.0676x over previous
#include <cuda_runtime.h>
#include <cstdint>

// Problem shape (fixed by the dataset)
#define BB 16
#define NN 512
#define FF 256
#define M_TOT (BB * NN)   // 8192

typedef unsigned long long ull;

// Scratch
__device__ float g_y[M_TOT * FF];      // adj @ x
__device__ float g_deg[M_TOT];         // rowsum(adj)

// ---- packed f32x2 helpers ---------------------------------------------------
#define PACK_X2(d, lo, hi) \
    asm("mov.b64 %0, {%1, %2};" : "=l"(d) : "r"(__float_as_uint(lo)), "r"(__float_as_uint(hi)))
#define UNPK_X2(lo, hi, s) do { unsigned _l, _h; \
    asm("mov.b64 {%0, %1}, %2;" : "=r"(_l), "=r"(_h) : "l"(s)); \
    lo = __uint_as_float(_l); hi = __uint_as_float(_h); } while (0)
#define ADD_X2I(acc, a) \
    asm("add.rn.f32x2 %0, %0, %1;" : "+l"(acc) : "l"(a))
#define FMA_X2I(acc, a, b) \
    asm("fma.rn.f32x2 %0, %1, %2, %0;" : "+l"(acc) : "l"(a), "l"(b))

// ---- cp.async helpers -------------------------------------------------------
__device__ __forceinline__ void cp_async16(unsigned saddr, const void* gptr) {
    asm volatile("cp.async.cg.shared.global [%0], [%1], 16;"
                 :: "r"(saddr), "l"(gptr));
}
#define CP_COMMIT() asm volatile("cp.async.commit_group;")
#define CP_WAIT(n)  asm volatile("cp.async.wait_group %0;" :: "n"(n))

// ---------------------------------------------------------------------------
// Kernel 1: y[b,i,f] = sum_j adj[b,i,j] * x[b,j,f]   deg[b,i] = rowsum
// Grid (NN/ICH, BB, 2): z = feature half. Warp owns 4 i-rows; lane owns 4
// features. x staged in 32-row double-buffered smem tiles via cp.async.
// Neighbor drain interleaves the 4 rows' masks -> 4 independent LDS chains.
// ---------------------------------------------------------------------------
#define ICH 32
#define JT  32
#define FH  128
#define TILE_F4 (JT * FH / 4)     // 1024 float4 per tile
#define NTILES  (NN / JT)         // 16

__global__ __launch_bounds__(256) void agg_x_kernel(
    const float* __restrict__ X,
    const float* __restrict__ ADJ,
    float* __restrict__ Y,
    float* __restrict__ DEG)
{
    extern __shared__ float xt[];   // 2 * JT*FH floats = 32 KB

    const int b    = blockIdx.y;
    const int i0   = blockIdx.x * ICH;
    const int fs   = blockIdx.z;
    const int t    = threadIdx.x;
    const int w    = t >> 5;
    const int lane = t & 31;

    const float4* xb4 = reinterpret_cast<const float4*>(X + (size_t)b * NN * FF + fs * FH);
    const unsigned sbase = (unsigned)__cvta_generic_to_shared(xt);

    ull acc2[4][2] = {{0ull,0ull},{0ull,0ull},{0ull,0ull},{0ull,0ull}};
    int degc[4] = {0, 0, 0, 0};

    const float* adj_base = ADJ + ((size_t)b * NN + i0 + w * 4) * NN + lane;

    // issue tile jt into buffer buf (4 x 16B per thread)
    auto issue = [&](int jt, int buf) {
#pragma unroll
        for (int p = 0; p < 4; p++) {
            int e   = t + p * 256;          // 0..1023
            int row = e >> 5;               // 0..31
            int c   = e & 31;               // float4 within row
            const float4* g = &xb4[(size_t)(jt * JT + row) * (FF / 4) + c];
            cp_async16(sbase + (unsigned)(buf * TILE_F4 + e) * 16u, g);
        }
        CP_COMMIT();
    };

    issue(0, 0);

    for (int jt = 0; jt < NTILES; jt++) {
        const int buf = jt & 1;
        if (jt + 1 < NTILES) {
            issue(jt + 1, buf ^ 1);
            CP_WAIT(1);
        } else {
            CP_WAIT(0);
        }
        __syncthreads();

        // adj values + masks for 4 rows (independent chains)
        float av[4];
#pragma unroll
        for (int ii = 0; ii < 4; ii++)
            av[ii] = adj_base[(size_t)ii * NN + jt * JT];
        unsigned m[4];
#pragma unroll
        for (int ii = 0; ii < 4; ii++) {
            m[ii] = __ballot_sync(0xffffffffu, av[ii] > 0.0f);
            degc[ii] += __popc(m[ii]);
        }

        const float* tb = xt + buf * (JT * FH) + lane * 4;
        while (m[0] | m[1] | m[2] | m[3]) {
#pragma unroll
            for (int ii = 0; ii < 4; ii++) {
                if (m[ii]) {
                    int j = __ffs(m[ii]) - 1;
                    m[ii] &= m[ii] - 1;
                    float4 h = *reinterpret_cast<const float4*>(tb + j * FH);
                    ull h01, h23;
                    PACK_X2(h01, h.x, h.y);
                    PACK_X2(h23, h.z, h.w);
                    ADD_X2I(acc2[ii][0], h01);
                    ADD_X2I(acc2[ii][1], h23);
                }
            }
        }
        __syncthreads();
    }

#pragma unroll
    for (int ii = 0; ii < 4; ii++) {
        const int m_ = b * NN + i0 + w * 4 + ii;
        float4 o;
        UNPK_X2(o.x, o.y, acc2[ii][0]);
        UNPK_X2(o.z, o.w, acc2[ii][1]);
        *reinterpret_cast<float4*>(Y + (size_t)m_ * FF + fs * FH + lane * 4) = o;
        if (fs == 0 && lane == 0) DEG[m_] = (float)degc[ii];
    }
}

// ---------------------------------------------------------------------------
// Kernel 2: fully fused GEMM + gate + blend.
//   hp[m,n]  = leaky( sum_k y[m,k]*W[n,k] + deg[m]*bias[n], 0.2 )   (in regs)
//   coeff[m] = sigmoid( x[m,:].gwx + hp[m,:].gwh + gb )
//   out      = coeff*x + (1-coeff)*hp
// BM=64, BN=256 (full row inside one warp), BK=16, 256 threads.
// warp ty owns rows ty*8..+7; lane tx owns cols {tx*4..+3, 128+tx*4..+3}.
// Reg-prefetch double buffering over 16 k-tiles. FFMA2 inner product.
// ---------------------------------------------------------------------------
#define GBM 64
#define GBK 16

__global__ __launch_bounds__(256) void gemm_fused_kernel(
    const float* __restrict__ Y,
    const float* __restrict__ W,
    const float* __restrict__ Wb,
    const float* __restrict__ DEG,
    const float* __restrict__ X,
    const float* __restrict__ GW,
    const float* __restrict__ GB,
    float* __restrict__ OUT)
{
    __shared__ float As[GBK][GBM];     // 4 KB
    __shared__ float Bs[GBK][FF];      // 16 KB

    const int t  = threadIdx.x;
    const int tx = t & 31;             // lane
    const int ty = t >> 5;             // warp
    const int m0 = blockIdx.x * GBM;

    const float4* Y4 = reinterpret_cast<const float4*>(Y);
    const float4* W4 = reinterpret_cast<const float4*>(W);

    // A prefetch: 64 rows x 4 float4 = 256 -> 1/thread
    const int ar = t >> 2, ac = t & 3;
    // B prefetch: 256 rows x 4 float4 = 1024 -> 4/thread

    float4 pa;
    float4 pb[4];

    auto loadT = [&](int kt4) {      // kt4 = kt/4
        pa = Y4[(size_t)(m0 + ar) * (FF / 4) + kt4 + ac];
#pragma unroll
        for (int p = 0; p < 4; p++) {
            int e = t + p * 256;
            pb[p] = W4[(size_t)(e >> 2) * (FF / 4) + kt4 + (e & 3)];
        }
    };
    auto storeT = [&]() {
        As[ac * 4 + 0][ar] = pa.x;
        As[ac * 4 + 1][ar] = pa.y;
        As[ac * 4 + 2][ar] = pa.z;
        As[ac * 4 + 3][ar] = pa.w;
#pragma unroll
        for (int p = 0; p < 4; p++) {
            int e = t + p * 256;
            int n = e >> 2, c = e & 3;
            Bs[c * 4 + 0][n] = pb[p].x;
            Bs[c * 4 + 1][n] = pb[p].y;
            Bs[c * 4 + 2][n] = pb[p].z;
            Bs[c * 4 + 3][n] = pb[p].w;
        }
    };

    ull acc2[4][8];
#pragma unroll
    for (int p = 0; p < 4; p++)
#pragma unroll
        for (int j = 0; j < 8; j++) acc2[p][j] = 0ull;

    loadT(0);
    for (int kt = 0; kt < FF / GBK; kt++) {
        storeT();
        __syncthreads();
        if (kt + 1 < FF / GBK) loadT((kt + 1) * (GBK / 4));   // overlaps compute

#pragma unroll
        for (int k = 0; k < GBK; k++) {
            float4 a0 = *reinterpret_cast<const float4*>(&As[k][ty * 8]);
            float4 a1 = *reinterpret_cast<const float4*>(&As[k][ty * 8 + 4]);
            float4 b0 = *reinterpret_cast<const float4*>(&Bs[k][tx * 4]);
            float4 b1 = *reinterpret_cast<const float4*>(&Bs[k][128 + tx * 4]);
            ull aa[4], bb[8];
            PACK_X2(aa[0], a0.x, a0.y);
            PACK_X2(aa[1], a0.z, a0.w);
            PACK_X2(aa[2], a1.x, a1.y);
            PACK_X2(aa[3], a1.z, a1.w);
            PACK_X2(bb[0], b0.x, b0.x);
            PACK_X2(bb[1], b0.y, b0.y);
            PACK_X2(bb[2], b0.z, b0.z);
            PACK_X2(bb[3], b0.w, b0.w);
            PACK_X2(bb[4], b1.x, b1.x);
            PACK_X2(bb[5], b1.y, b1.y);
            PACK_X2(bb[6], b1.z, b1.z);
            PACK_X2(bb[7], b1.w, b1.w);
#pragma unroll
            for (int p = 0; p < 4; p++)
#pragma unroll
                for (int j = 0; j < 8; j++)
                    FMA_X2I(acc2[p][j], aa[p], bb[j]);
        }
        __syncthreads();
    }

    // ---- fused epilogue: deg*bias, leaky, gate, sigmoid, blend, store ----
    float4 bias0 = *reinterpret_cast<const float4*>(&Wb[tx * 4]);
    float4 bias1 = *reinterpret_cast<const float4*>(&Wb[128 + tx * 4]);
    float4 gwx0  = *reinterpret_cast<const float4*>(&GW[tx * 4]);
    float4 gwx1  = *reinterpret_cast<const float4*>(&GW[128 + tx * 4]);
    float4 gwh0  = *reinterpret_cast<const float4*>(&GW[FF + tx * 4]);
    float4 gwh1  = *reinterpret_cast<const float4*>(&GW[FF + 128 + tx * 4]);
    const float gb = GB[0];
    const float bias[8] = {bias0.x, bias0.y, bias0.z, bias0.w,
                           bias1.x, bias1.y, bias1.z, bias1.w};
    const float gwh[8]  = {gwh0.x, gwh0.y, gwh0.z, gwh0.w,
                           gwh1.x, gwh1.y, gwh1.z, gwh1.w};
    const float gwx[8]  = {gwx0.x, gwx0.y, gwx0.z, gwx0.w,
                           gwx1.x, gwx1.y, gwx1.z, gwx1.w};

#pragma unroll
    for (int p = 0; p < 4; p++) {
        float rlo[8], rhi[8];
#pragma unroll
        for (int j = 0; j < 8; j++) UNPK_X2(rlo[j], rhi[j], acc2[p][j]);

#pragma unroll
        for (int s = 0; s < 2; s++) {
            const int m = m0 + ty * 8 + p * 2 + s;
            const float dg = DEG[m];
            float* rr = s ? rhi : rlo;

            float hp[8];
#pragma unroll
            for (int j = 0; j < 8; j++) {
                float v = rr[j] + dg * bias[j];
                hp[j] = (v > 0.0f) ? v : 0.2f * v;
            }

            const float* xr = X + (size_t)m * FF;
            float4 x0 = *reinterpret_cast<const float4*>(xr + tx * 4);
            float4 x1 = *reinterpret_cast<const float4*>(xr + 128 + tx * 4);
            float xv[8] = {x0.x, x0.y, x0.z, x0.w, x1.x, x1.y, x1.z, x1.w};

            float g = 0.0f;
#pragma unroll
            for (int j = 0; j < 8; j++)
                g += xv[j] * gwx[j] + hp[j] * gwh[j];
#pragma unroll
            for (int off = 16; off > 0; off >>= 1)
                g += __shfl_xor_sync(0xffffffffu, g, off);

            float coeff = 1.0f / (1.0f + expf(-(g + gb)));
            float om = 1.0f - coeff;

            float4 o0, o1;
            o0.x = coeff * xv[0] + om * hp[0];
            o0.y = coeff * xv[1] + om * hp[1];
            o0.z = coeff * xv[2] + om * hp[2];
            o0.w = coeff * xv[3] + om * hp[3];
            o1.x = coeff * xv[4] + om * hp[4];
            o1.y = coeff * xv[5] + om * hp[5];
            o1.z = coeff * xv[6] + om * hp[6];
            o1.w = coeff * xv[7] + om * hp[7];

            float* orow = OUT + (size_t)m * FF;
            *reinterpret_cast<float4*>(orow + tx * 4)       = o0;
            *reinterpret_cast<float4*>(orow + 128 + tx * 4) = o1;
        }
    }
}

// ---------------------------------------------------------------------------
extern "C" void kernel_launch(void* const* d_in, const int* in_sizes, int n_in,
                              void* d_out, int out_size)
{
    const float* x    = (const float*)d_in[0];   // [16,512,256]
    const float* adj  = (const float*)d_in[1];   // [16,512,512]
    const float* W_w  = (const float*)d_in[2];   // [256,256]
    const float* W_b  = (const float*)d_in[3];   // [256]
    // d_in[4] = A : dead code in the reference
    const float* gw   = (const float*)d_in[5];   // [1,512]
    const float* gb   = (const float*)d_in[6];   // [1]
    float* out = (float*)d_out;

    float* y;   cudaGetSymbolAddress((void**)&y,   g_y);
    float* deg; cudaGetSymbolAddress((void**)&deg, g_deg);

    const int smem1 = 2 * JT * FH * sizeof(float);   // 32 KB
    cudaFuncSetAttribute(agg_x_kernel,
                         cudaFuncAttributeMaxDynamicSharedMemorySize, smem1);
    dim3 grid1(NN / ICH, BB, 2);                 // 512 CTAs
    agg_x_kernel<<<grid1, 256, smem1>>>(x, adj, y, deg);

    gemm_fused_kernel<<<M_TOT / GBM, 256>>>(y, W_w, W_b, deg, x, gw, gb, out);
}